// round 14
// baseline (speedup 1.0000x reference)
#include <cuda_runtime.h>
#include <cuda_bf16.h>
#include <math.h>
#include <stdint.h>

#define B_ 64
#define N_ 512
#define D_ 128
#define K_ 32
#define M_ (B_ * N_)
#define EPS_ 1e-5f

typedef unsigned long long ull;
typedef unsigned short ushort_t;

// ---------------- device scratch ----------------
__device__ float g_xlin[M_ * D_];
__device__ float g_si[M_];
__device__ float g_sj[M_];
__device__ float g_ei[N_];
__device__ float g_ej[N_];
__device__ float g_cos[N_ * N_];
__device__ int   g_topk[N_ * K_];
__device__ float g_agg[M_ * D_];
__device__ float g_h[M_ * D_];
__device__ float g_o1[M_ * 256];
__device__ float g_o2[M_ * 256];
// W images: [n][k] row-major bf16, hi/lo split
__device__ __nv_bfloat16 g_Wh0[128 * 128], g_Wl0[128 * 128];
__device__ __nv_bfloat16 g_Wh1[256 * 128], g_Wl1[256 * 128];
__device__ __nv_bfloat16 g_Wh2[256 * 256], g_Wl2[256 * 256];
// stats: [0]=agg sum(128) [128]=agg sq [256]=h sum [384]=h sq
//        [512]=o1 sum(256) [768]=o1 sq [1024]=o2 sum [1280]=o2 sq
__device__ float g_red[1536];

// ---------------- helpers ----------------
__device__ __forceinline__ uint32_t smem_to_u32(const void* p) {
    uint32_t a;
    asm("{ .reg .u64 t; cvta.to.shared.u64 t, %1; cvt.u32.u64 %0, t; }"
        : "=r"(a) : "l"(p));
    return a;
}
__device__ __forceinline__ ushort_t bf_hi(float f, ushort_t& lo) {
    __nv_bfloat16 h = __float2bfloat16(f);
    float r = f - __bfloat162float(h);
    lo = __bfloat16_as_ushort(__float2bfloat16(r));
    return __bfloat16_as_ushort(h);
}
__device__ __forceinline__ ull pack4(ushort_t a, ushort_t b, ushort_t c, ushort_t d) {
    return (ull)a | ((ull)b << 16) | ((ull)c << 32) | ((ull)d << 48);
}
#define LDSM_X4(r0, r1, r2, r3, addr) \
    asm volatile("ldmatrix.sync.aligned.m8n8.x4.shared.b16 {%0,%1,%2,%3}, [%4];" \
                 : "=r"(r0), "=r"(r1), "=r"(r2), "=r"(r3) : "r"(addr))
#define MMA(dd, aa, b0v, b1v) \
    asm volatile("mma.sync.aligned.m16n8k16.row.col.f32.bf16.bf16.f32 " \
                 "{%0,%1,%2,%3}, {%4,%5,%6,%7}, {%8,%9}, {%0,%1,%2,%3};" \
                 : "+f"((dd)[0]), "+f"((dd)[1]), "+f"((dd)[2]), "+f"((dd)[3]) \
                 : "r"((aa)[0]), "r"((aa)[1]), "r"((aa)[2]), "r"((aa)[3]), \
                   "r"(b0v), "r"(b1v))

// ---------------- gram + init fused -----------------------------------------
__global__ __launch_bounds__(256) void k_graminit(const float* __restrict__ emb,
                                                  const float* __restrict__ linW,
                                                  const float* __restrict__ W1,
                                                  const float* __restrict__ W2,
                                                  const float* __restrict__ aei,
                                                  const float* __restrict__ aej) {
    __shared__ float Ash[128][32];
    __shared__ float Bsh[128][64];
    __shared__ float inviS[32], invjS[64];
    int t = threadIdx.x;
    int bx = blockIdx.x, by = blockIdx.y;
    int bid = by * 16 + bx;
    int gid = bid * 256 + t;

    if (gid < 1536) g_red[gid] = 0.0f;
    for (int id = gid; id < 114688; id += 32768) {
        if (id < 16384) {
            int k = id >> 7, n = id & 127;
            ushort_t lo; ushort_t hi = bf_hi(linW[k * 128 + n], lo);
            g_Wh0[n * 128 + k] = __ushort_as_bfloat16(hi);
            g_Wl0[n * 128 + k] = __ushort_as_bfloat16(lo);
        } else if (id < 49152) {
            int e = id - 16384;
            int k = e >> 8, n = e & 255;
            ushort_t lo; ushort_t hi = bf_hi(W1[k * 256 + n], lo);
            g_Wh1[n * 128 + k] = __ushort_as_bfloat16(hi);
            g_Wl1[n * 128 + k] = __ushort_as_bfloat16(lo);
        } else {
            int e = id - 49152;
            int k = e >> 8, n = e & 255;
            ushort_t lo; ushort_t hi = bf_hi(W2[k * 256 + n], lo);
            g_Wh2[n * 256 + k] = __ushort_as_bfloat16(hi);
            g_Wl2[n * 256 + k] = __ushort_as_bfloat16(lo);
        }
    }
    if (bid < 64) {
        int w = t >> 5, lane = t & 31;
        int n = bid * 8 + w;
        float4 v4 = *(const float4*)&emb[n * D_ + lane * 4];
        float4 ai4 = *(const float4*)&aei[lane * 4];
        float4 aj4 = *(const float4*)&aej[lane * 4];
        float pi = v4.x * ai4.x + v4.y * ai4.y + v4.z * ai4.z + v4.w * ai4.w;
        float pj = v4.x * aj4.x + v4.y * aj4.y + v4.z * aj4.z + v4.w * aj4.w;
        #pragma unroll
        for (int o = 16; o > 0; o >>= 1) {
            pi += __shfl_xor_sync(0xffffffffu, pi, o);
            pj += __shfl_xor_sync(0xffffffffu, pj, o);
        }
        if (lane == 0) { g_ei[n] = pi; g_ej[n] = pj; }
    }

    int i0 = bx * 32, j0 = by * 64;
    {
        int r = t & 31, kq0 = t >> 5;
        #pragma unroll
        for (int q = 0; q < 4; q++) {
            int kq = kq0 + q * 8;
            float4 a = *(const float4*)&emb[(i0 + r) * 128 + kq * 4];
            Ash[kq * 4 + 0][r] = a.x; Ash[kq * 4 + 1][r] = a.y;
            Ash[kq * 4 + 2][r] = a.z; Ash[kq * 4 + 3][r] = a.w;
        }
    }
    {
        int r = t & 63, kq0 = t >> 6;
        #pragma unroll
        for (int q = 0; q < 8; q++) {
            int kq = kq0 + q * 4;
            float4 b = *(const float4*)&emb[(j0 + r) * 128 + kq * 4];
            Bsh[kq * 4 + 0][r] = b.x; Bsh[kq * 4 + 1][r] = b.y;
            Bsh[kq * 4 + 2][r] = b.z; Bsh[kq * 4 + 3][r] = b.w;
        }
    }
    __syncthreads();
    if (t < 32) {
        float s = 0.0f;
        #pragma unroll 8
        for (int k = 0; k < 128; k++) { float v = Ash[k][t]; s += v * v; }
        inviS[t] = 1.0f / sqrtf(s);
    } else if (t < 96) {
        int r = t - 32;
        float s = 0.0f;
        #pragma unroll 8
        for (int k = 0; k < 128; k++) { float v = Bsh[k][r]; s += v * v; }
        invjS[r] = 1.0f / sqrtf(s);
    }
    __syncthreads();
    int tr = t >> 4, tc = t & 15;
    float acc[2][4] = {};
    #pragma unroll 4
    for (int k = 0; k < 128; k++) {
        float2 av = *(float2*)&Ash[k][tr * 2];
        float4 bv = *(float4*)&Bsh[k][tc * 4];
        acc[0][0] += av.x * bv.x; acc[0][1] += av.x * bv.y;
        acc[0][2] += av.x * bv.z; acc[0][3] += av.x * bv.w;
        acc[1][0] += av.y * bv.x; acc[1][1] += av.y * bv.y;
        acc[1][2] += av.y * bv.z; acc[1][3] += av.y * bv.w;
    }
    float invi[2], invj[4];
    #pragma unroll
    for (int q = 0; q < 2; q++) invi[q] = inviS[tr * 2 + q];
    #pragma unroll
    for (int q = 0; q < 4; q++) invj[q] = invjS[tc * 4 + q];
    #pragma unroll
    for (int rr = 0; rr < 2; rr++) {
        float s = invi[rr];
        *(float4*)&g_cos[(i0 + tr * 2 + rr) * N_ + j0 + tc * 4] =
            make_float4(acc[rr][0] * s * invj[0], acc[rr][1] * s * invj[1],
                        acc[rr][2] * s * invj[2], acc[rr][3] * s * invj[3]);
    }
}

// ---------------- topk selection: one warp per row, 128 blocks --------------
__global__ __launch_bounds__(128) void k_sel() {
    __shared__ float sv[4][512];
    int t = threadIdx.x, w = t >> 5, lane = t & 31;
    int i = blockIdx.x * 4 + w;
    float* v = sv[w];
    #pragma unroll
    for (int q = 0; q < 16; q++)
        v[q * 32 + lane] = g_cos[i * N_ + q * 32 + lane];
    float lv = v[lane]; int li = 0;
    #pragma unroll
    for (int q = 1; q < 16; q++) {
        float x = v[q * 32 + lane];
        if (x > lv) { lv = x; li = q; }
    }
    for (int k = 0; k < K_; k++) {
        float bv = lv;
        int bj = li * 32 + lane;
        #pragma unroll
        for (int o = 16; o > 0; o >>= 1) {
            float ov = __shfl_xor_sync(0xffffffffu, bv, o);
            int oj = __shfl_xor_sync(0xffffffffu, bj, o);
            if (ov > bv || (ov == bv && oj < bj)) { bv = ov; bj = oj; }
        }
        if (lane == 0) g_topk[i * K_ + k] = bj;
        if ((bj & 31) == lane) {
            v[bj] = -2.0f;
            lv = v[lane]; li = 0;
            #pragma unroll
            for (int q = 1; q < 16; q++) {
                float x = v[q * 32 + lane];
                if (x > lv) { lv = x; li = q; }
            }
        }
        __syncwarp();
    }
}

// ---------------- unified HMMA GEMM (3-term bf16 split, R10 config) ---------
template <int PASS>
__global__ __launch_bounds__(256) void k_gemm(const float* __restrict__ Xext,
                                              const float* __restrict__ gin,
                                              const float* __restrict__ bin) {
    constexpr int KD   = (PASS == 2) ? 256 : 128;
    constexpr int OSTR = (PASS == 0) ? 128 : 256;
    constexpr int SIN  = (PASS == 1) ? 256 : 512;
    constexpr int SOUT = (PASS == 1) ? 512 : 1024;

    __shared__ __align__(16) __nv_bfloat16 Xh[128 * 40];
    __shared__ __align__(16) __nv_bfloat16 Xl[128 * 40];
    __shared__ __align__(16) __nv_bfloat16 Wh[128 * 40];
    __shared__ __align__(16) __nv_bfloat16 Wl[128 * 40];
    __shared__ float nsc[256], nsh[256];
    __shared__ float sbS[4][128], sbQ[4][128];

    const float* __restrict__ Xg =
        (PASS == 0) ? Xext : ((PASS == 1) ? g_h : g_o1);
    float* __restrict__ outg =
        (PASS == 0) ? g_xlin : ((PASS == 1) ? g_o1 : g_o2);
    const __nv_bfloat16* Wgh = (PASS == 0) ? g_Wh0 : ((PASS == 1) ? g_Wh1 : g_Wh2);
    const __nv_bfloat16* Wgl = (PASS == 0) ? g_Wl0 : ((PASS == 1) ? g_Wl1 : g_Wl2);

    int t = threadIdx.x, l = t & 31, w = t >> 5;
    int wr = w >> 1, wc = w & 1;
    int row0 = blockIdx.x * 128;
    int nb = blockIdx.y;
    const __nv_bfloat16* WghB = Wgh + nb * 128 * KD;
    const __nv_bfloat16* WglB = Wgl + nb * 128 * KD;

    if (PASS != 0) {
        const float invM = 1.0f / (float)M_;
        if (t < KD) {
            float mean = g_red[SIN + t] * invM;
            float var  = g_red[SIN + KD + t] * invM - mean * mean;
            float s = rsqrtf(var + EPS_) * gin[t];
            nsc[t] = s; nsh[t] = bin[t] - mean * s;
        }
        __syncthreads();
    } else {
        if (t < 128) { nsc[t] = gin[t]; nsh[t] = bin[t]; }  // att_i, att_j
        __syncthreads();
    }

    float d[2][8][4] = {};
    uint32_t xh_b = smem_to_u32(Xh), xl_b = smem_to_u32(Xl);
    uint32_t wh_b = smem_to_u32(Wh), wl_b = smem_to_u32(Wl);

    for (int kb = 0; kb < KD; kb += 32) {
        #pragma unroll
        for (int v = t; v < 1024; v += 256) {
            int r = v >> 3, k4 = (v & 7) * 4;
            float4 x4 = *(const float4*)&Xg[(row0 + r) * KD + kb + k4];
            float f0, f1, f2, f3;
            if (PASS == 0) {
                f0 = x4.x; f1 = x4.y; f2 = x4.z; f3 = x4.w;
            } else {
                int fc = kb + k4;
                f0 = fmaxf(x4.x * nsc[fc + 0] + nsh[fc + 0], 0.0f);
                f1 = fmaxf(x4.y * nsc[fc + 1] + nsh[fc + 1], 0.0f);
                f2 = fmaxf(x4.z * nsc[fc + 2] + nsh[fc + 2], 0.0f);
                f3 = fmaxf(x4.w * nsc[fc + 3] + nsh[fc + 3], 0.0f);
            }
            ushort_t l0, l1, l2, l3;
            ushort_t h0 = bf_hi(f0, l0), h1 = bf_hi(f1, l1);
            ushort_t h2 = bf_hi(f2, l2), h3 = bf_hi(f3, l3);
            *(ull*)(&Xh[r * 40 + k4]) = pack4(h0, h1, h2, h3);
            *(ull*)(&Xl[r * 40 + k4]) = pack4(l0, l1, l2, l3);
        }
        #pragma unroll
        for (int v = t; v < 512; v += 256) {
            int n = v >> 2, k8 = (v & 3) * 8;
            *(float4*)&Wh[n * 40 + k8] = *(const float4*)&WghB[n * KD + kb + k8];
            *(float4*)&Wl[n * 40 + k8] = *(const float4*)&WglB[n * KD + kb + k8];
        }
        __syncthreads();
        #pragma unroll
        for (int ks = 0; ks < 32; ks += 16) {
            uint32_t ah[2][4], al[2][4];
            uint32_t arow = (uint32_t)(l & 15);
            uint32_t akoff = (uint32_t)((l >> 4) << 3);
            #pragma unroll
            for (int mt = 0; mt < 2; mt++) {
                uint32_t off = ((wr * 32 + mt * 16 + arow) * 40 + ks + akoff) * 2;
                LDSM_X4(ah[mt][0], ah[mt][1], ah[mt][2], ah[mt][3], xh_b + off);
                LDSM_X4(al[mt][0], al[mt][1], al[mt][2], al[mt][3], xl_b + off);
            }
            uint32_t brow = (uint32_t)(((l >> 4) << 3) + (l & 7));
            uint32_t bkoff = (uint32_t)(((l >> 3) & 1) << 3);
            #pragma unroll
            for (int g = 0; g < 4; g++) {
                uint32_t off = ((wc * 64 + g * 16 + brow) * 40 + ks + bkoff) * 2;
                uint32_t bh[4], bl[4];
                LDSM_X4(bh[0], bh[1], bh[2], bh[3], wh_b + off);
                LDSM_X4(bl[0], bl[1], bl[2], bl[3], wl_b + off);
                MMA(d[0][2 * g],     ah[0], bh[0], bh[1]);
                MMA(d[0][2 * g + 1], ah[0], bh[2], bh[3]);
                MMA(d[1][2 * g],     ah[1], bh[0], bh[1]);
                MMA(d[1][2 * g + 1], ah[1], bh[2], bh[3]);
                MMA(d[0][2 * g],     ah[0], bl[0], bl[1]);
                MMA(d[0][2 * g + 1], ah[0], bl[2], bl[3]);
                MMA(d[1][2 * g],     ah[1], bl[0], bl[1]);
                MMA(d[1][2 * g + 1], ah[1], bl[2], bl[3]);
                MMA(d[0][2 * g],     al[0], bh[0], bh[1]);
                MMA(d[0][2 * g + 1], al[0], bh[2], bh[3]);
                MMA(d[1][2 * g],     al[1], bh[0], bh[1]);
                MMA(d[1][2 * g + 1], al[1], bh[2], bh[3]);
            }
        }
        __syncthreads();
    }

    int rbase = row0 + wr * 32 + (l >> 2);
    int cbase = nb * 128 + wc * 64 + (l & 3) * 2;
    #pragma unroll
    for (int mt = 0; mt < 2; mt++) {
        #pragma unroll
        for (int nt = 0; nt < 8; nt++) {
            int col = cbase + nt * 8;
            *(float2*)&outg[(rbase + mt * 16) * OSTR + col] =
                make_float2(d[mt][nt][0], d[mt][nt][1]);
            *(float2*)&outg[(rbase + mt * 16 + 8) * OSTR + col] =
                make_float2(d[mt][nt][2], d[mt][nt][3]);
        }
    }
    if (PASS != 0) {
        #pragma unroll
        for (int nt = 0; nt < 8; nt++) {
            float c0 = d[0][nt][0] + d[0][nt][2] + d[1][nt][0] + d[1][nt][2];
            float c1 = d[0][nt][1] + d[0][nt][3] + d[1][nt][1] + d[1][nt][3];
            float q0 = d[0][nt][0] * d[0][nt][0] + d[0][nt][2] * d[0][nt][2] +
                       d[1][nt][0] * d[1][nt][0] + d[1][nt][2] * d[1][nt][2];
            float q1 = d[0][nt][1] * d[0][nt][1] + d[0][nt][3] * d[0][nt][3] +
                       d[1][nt][1] * d[1][nt][1] + d[1][nt][3] * d[1][nt][3];
            #pragma unroll
            for (int o = 4; o <= 16; o <<= 1) {
                c0 += __shfl_xor_sync(0xffffffffu, c0, o);
                c1 += __shfl_xor_sync(0xffffffffu, c1, o);
                q0 += __shfl_xor_sync(0xffffffffu, q0, o);
                q1 += __shfl_xor_sync(0xffffffffu, q1, o);
            }
            if (l < 4) {
                sbS[wr][wc * 64 + nt * 8 + l * 2]     = c0;
                sbS[wr][wc * 64 + nt * 8 + l * 2 + 1] = c1;
                sbQ[wr][wc * 64 + nt * 8 + l * 2]     = q0;
                sbQ[wr][wc * 64 + nt * 8 + l * 2 + 1] = q1;
            }
        }
        __syncthreads();
        if (t < 128) {
            float S = sbS[0][t] + sbS[1][t] + sbS[2][t] + sbS[3][t];
            float Q = sbQ[0][t] + sbQ[1][t] + sbQ[2][t] + sbQ[3][t];
            atomicAdd(&g_red[SOUT + nb * 128 + t], S);
            atomicAdd(&g_red[SOUT + 256 + nb * 128 + t], Q);
        }
    } else {
        #pragma unroll
        for (int mt = 0; mt < 2; mt++) {
            float p0 = 0, p1 = 0, pj0 = 0, pj1 = 0;
            #pragma unroll
            for (int nt = 0; nt < 8; nt++) {
                int c = wc * 64 + (l & 3) * 2 + nt * 8;
                p0  += d[mt][nt][0] * nsc[c] + d[mt][nt][1] * nsc[c + 1];
                p1  += d[mt][nt][2] * nsc[c] + d[mt][nt][3] * nsc[c + 1];
                pj0 += d[mt][nt][0] * nsh[c] + d[mt][nt][1] * nsh[c + 1];
                pj1 += d[mt][nt][2] * nsh[c] + d[mt][nt][3] * nsh[c + 1];
            }
            #pragma unroll
            for (int o = 1; o <= 2; o <<= 1) {
                p0  += __shfl_xor_sync(0xffffffffu, p0, o);
                p1  += __shfl_xor_sync(0xffffffffu, p1, o);
                pj0 += __shfl_xor_sync(0xffffffffu, pj0, o);
                pj1 += __shfl_xor_sync(0xffffffffu, pj1, o);
            }
            if ((l & 3) == 0) {
                int rl = wr * 32 + mt * 16 + (l >> 2);
                sbS[wc * 2][rl]     = p0;
                sbS[wc * 2][rl + 8] = p1;
                sbQ[wc * 2][rl]     = pj0;
                sbQ[wc * 2][rl + 8] = pj1;
            }
        }
        __syncthreads();
        if (t < 128) {
            int row = row0 + t;
            int n = row & (N_ - 1);
            g_si[row] = sbS[0][t] + sbS[2][t] + g_ei[n];
            g_sj[row] = sbQ[0][t] + sbQ[2][t] + g_ej[n];
        }
    }
}

// ---------------- attention v4: paired compacted lists + 4 windows ----------
// grid (4, B_), 512 threads. smem (floats):
// [0,16384)        xwin: 128x128 fp32 (64KB)
// [16384,26112)    list: float2[128][38] (alpha, byte-offset), segments
//                  padded to even length with exact-zero edges
// [26112,26752)    cb: int[128][5]
#define ATTN3_FLOATS (16384 + 9728 + 640)
__global__ __launch_bounds__(512, 2) void k_attn3() {
    extern __shared__ float dsm[];
    float*  xwin = dsm;
    float2* list = (float2*)(dsm + 16384);
    int*    cb   = (int*)(dsm + 16384 + 9728);

    int t = threadIdx.x, lane = t & 31, w = t >> 5;  // 16 warps
    int b = blockIdx.y, i0 = blockIdx.x * 128;

    // ---- build per-node compacted edge lists, even-padded per window ----
    #pragma unroll
    for (int q = 0; q < 8; q++) {
        int mi = w * 8 + q;
        int i = i0 + mi;
        int m = b * N_ + i;
        int src = g_topk[i * K_ + lane];
        float sim = g_si[m];
        float v = sim + g_sj[b * N_ + src];
        float lg = v > 0.0f ? v : 0.2f * v;
        bool valid = (src != i);
        if (!valid) lg = -1e30f;
        float vs = sim + g_sj[m];
        float lgs = vs > 0.0f ? vs : 0.2f * vs;   // explicit self loop
        float mx = lg;
        #pragma unroll
        for (int o = 16; o > 0; o >>= 1)
            mx = fmaxf(mx, __shfl_xor_sync(0xffffffffu, mx, o));
        mx = fmaxf(mx, lgs);
        float e = valid ? expf(lg - mx) : 0.0f;
        float es = expf(lgs - mx);
        float den = e;
        #pragma unroll
        for (int o = 16; o > 0; o >>= 1)
            den += __shfl_xor_sync(0xffffffffu, den, o);
        den += es;
        float alpha = e / den;
        float aself = es / den;
        int win = src >> 7;
        int selfwin = i >> 7;
        unsigned lt = (1u << lane) - 1u;
        int base = 0;
        #pragma unroll
        for (int wn = 0; wn < 4; wn++) {
            unsigned mk = __ballot_sync(0xffffffffu, valid && win == wn);
            int selfhere = (selfwin == wn) ? 1 : 0;
            if (lane == 0) cb[mi * 5 + wn] = base;
            if (valid && win == wn) {
                int pos = base + __popc(mk & lt);
                list[mi * 38 + pos] =
                    make_float2(alpha, __uint_as_float((uint32_t)((src & 127) * 512)));
            }
            int cnt = __popc(mk) + selfhere;
            if (lane == 0) {
                if (selfhere)
                    list[mi * 38 + base + __popc(mk)] =
                        make_float2(aself, __uint_as_float((uint32_t)((i & 127) * 512)));
                if (cnt & 1)
                    list[mi * 38 + base + cnt] = make_float2(0.0f, __uint_as_float(0u));
            }
            base += (cnt + 1) & ~1;     // even-pad
        }
        if (lane == 0) cb[mi * 5 + 4] = base;
    }

    uint32_t xwin_b = smem_to_u32(xwin);
    float acc[8][4] = {};
    for (int win = 0; win < 4; win++) {
        __syncthreads();
        const float4* srcp = (const float4*)&g_xlin[(b * N_ + win * 128) * D_];
        #pragma unroll
        for (int v = t; v < 4096; v += 512)
            ((float4*)xwin)[v] = srcp[v];
        __syncthreads();
        uint32_t loff = (uint32_t)(lane * 16);
        #pragma unroll
        for (int q = 0; q < 8; q++) {
            int mi = w * 8 + q;
            int s = cb[mi * 5 + win] >> 1, e = cb[mi * 5 + win + 1] >> 1;
            const float4* lp4 = (const float4*)&list[mi * 38];
            for (int p = s; p < e; p++) {
                float4 cv = lp4[p];                       // 2 edges, broadcast
                uint32_t o0 = __float_as_uint(cv.y);
                uint32_t o1 = __float_as_uint(cv.w);
                float a0 = cv.x, a1 = cv.z;
                float4 x0, x1;
                asm volatile("ld.shared.v4.f32 {%0,%1,%2,%3}, [%4];"
                             : "=f"(x0.x), "=f"(x0.y), "=f"(x0.z), "=f"(x0.w)
                             : "r"(xwin_b + o0 + loff));
                asm volatile("ld.shared.v4.f32 {%0,%1,%2,%3}, [%4];"
                             : "=f"(x1.x), "=f"(x1.y), "=f"(x1.z), "=f"(x1.w)
                             : "r"(xwin_b + o1 + loff));
                acc[q][0] += a0 * x0.x; acc[q][1] += a0 * x0.y;
                acc[q][2] += a0 * x0.z; acc[q][3] += a0 * x0.w;
                acc[q][0] += a1 * x1.x; acc[q][1] += a1 * x1.y;
                acc[q][2] += a1 * x1.z; acc[q][3] += a1 * x1.w;
            }
        }
    }
    __syncthreads();
    // ---- write agg + fused stats (reuse xwin region) ----
    float s[4] = {}, qd[4] = {};
    #pragma unroll
    for (int q = 0; q < 8; q++) {
        int m = b * N_ + i0 + w * 8 + q;
        *(float4*)&g_agg[m * D_ + lane * 4] =
            make_float4(acc[q][0], acc[q][1], acc[q][2], acc[q][3]);
        #pragma unroll
        for (int c = 0; c < 4; c++) { s[c] += acc[q][c]; qd[c] += acc[q][c] * acc[q][c]; }
    }
    float* sS = dsm;
    float* sQ = dsm + 2048;
    #pragma unroll
    for (int c = 0; c < 4; c++) {
        sS[w * 128 + lane * 4 + c] = s[c];
        sQ[w * 128 + lane * 4 + c] = qd[c];
    }
    __syncthreads();
    if (t < 128) {
        float S = 0, Q = 0;
        #pragma unroll
        for (int g = 0; g < 16; g++) { S += sS[g * 128 + t]; Q += sQ[g * 128 + t]; }
        atomicAdd(&g_red[t], S);
        atomicAdd(&g_red[128 + t], Q);
    }
}

// ---------------- gcn = relu(bn(agg)); h = gcn*emb + h stats ----------------
// 1024 blocks x 256 threads; warp handles 4 rows.
__global__ __launch_bounds__(256) void k_h(const float* __restrict__ emb,
                                           const float* __restrict__ g0,
                                           const float* __restrict__ b0) {
    __shared__ float sS[8][128], sQ[8][128];
    int t = threadIdx.x, w = t >> 5, lane = t & 31;
    int r0 = blockIdx.x * 32 + w * 4;
    const float invM = 1.0f / (float)M_;
    int d4 = lane * 4;
    float4 sm = *(float4*)&g_red[d4];
    float4 sq = *(float4*)&g_red[D_ + d4];
    float4 gg = *(const float4*)&g0[d4];
    float4 bb = *(const float4*)&b0[d4];
    float mean0 = sm.x * invM, mean1 = sm.y * invM, mean2 = sm.z * invM, mean3 = sm.w * invM;
    float sc0 = rsqrtf(sq.x * invM - mean0 * mean0 + EPS_) * gg.x;
    float sc1 = rsqrtf(sq.y * invM - mean1 * mean1 + EPS_) * gg.y;
    float sc2 = rsqrtf(sq.z * invM - mean2 * mean2 + EPS_) * gg.z;
    float sc3 = rsqrtf(sq.w * invM - mean3 * mean3 + EPS_) * gg.w;
    float sh0 = bb.x - mean0 * sc0, sh1 = bb.y - mean1 * sc1;
    float sh2 = bb.z - mean2 * sc2, sh3 = bb.w - mean3 * sc3;
    float S[4] = {}, Q[4] = {};
    #pragma unroll
    for (int r = 0; r < 4; r++) {
        int row = r0 + r;
        float4 a = *(float4*)&g_agg[row * D_ + d4];
        float4 e = *(const float4*)&emb[(row & (N_ - 1)) * D_ + d4];
        float h0 = fmaxf(a.x * sc0 + sh0, 0.0f) * e.x;
        float h1 = fmaxf(a.y * sc1 + sh1, 0.0f) * e.y;
        float h2 = fmaxf(a.z * sc2 + sh2, 0.0f) * e.z;
        float h3 = fmaxf(a.w * sc3 + sh3, 0.0f) * e.w;
        *(float4*)&g_h[row * D_ + d4] = make_float4(h0, h1, h2, h3);
        S[0] += h0; S[1] += h1; S[2] += h2; S[3] += h3;
        Q[0] += h0 * h0; Q[1] += h1 * h1; Q[2] += h2 * h2; Q[3] += h3 * h3;
    }
    #pragma unroll
    for (int c = 0; c < 4; c++) { sS[w][d4 + c] = S[c]; sQ[w][d4 + c] = Q[c]; }
    __syncthreads();
    if (t < 128) {
        float Ss = 0, Qs = 0;
        #pragma unroll
        for (int g = 0; g < 8; g++) { Ss += sS[g][t]; Qs += sQ[g][t]; }
        atomicAdd(&g_red[256 + t], Ss);
        atomicAdd(&g_red[384 + t], Qs);
    }
}

// ---------------- final: out = relu(bn(o2)) @ W3 + b3 ----------------
__global__ __launch_bounds__(256) void k_out(const float* __restrict__ W3,
                                             const float* __restrict__ b3,
                                             const float* __restrict__ g2,
                                             const float* __restrict__ b2v,
                                             float* __restrict__ out) {
    __shared__ float nsc[256], nsh[256], w[256];
    int t = threadIdx.x;
    const float invM = 1.0f / (float)M_;
    {
        float mean = g_red[1024 + t] * invM;
        float var  = g_red[1280 + t] * invM - mean * mean;
        float s = rsqrtf(var + EPS_) * g2[t];
        nsc[t] = s; nsh[t] = b2v[t] - mean * s; w[t] = W3[t];
    }
    __syncthreads();
    int warp = t >> 5, lane = t & 31;
    int m = blockIdx.x * 8 + warp;
    float acc = 0.0f;
    #pragma unroll
    for (int f = lane; f < 256; f += 32) {
        float v = g_o2[m * 256 + f];
        acc += fmaxf(v * nsc[f] + nsh[f], 0.0f) * w[f];
    }
    for (int o = 16; o > 0; o >>= 1)
        acc += __shfl_xor_sync(0xffffffffu, acc, o);
    if (lane == 0) out[m] = acc + b3[0];
}

// ---------------- launch ----------------
extern "C" void kernel_launch(void* const* d_in, const int* in_sizes, int n_in,
                              void* d_out, int out_size) {
    const float* data   = (const float*)d_in[0];
    const float* emb    = (const float*)d_in[1];
    const float* lin_W  = (const float*)d_in[2];
    const float* att_i  = (const float*)d_in[3];
    const float* att_j  = (const float*)d_in[4];
    const float* aem_i  = (const float*)d_in[5];
    const float* aem_j  = (const float*)d_in[6];
    // d_in[7] = gnn_bias : cancels exactly under BN
    const float* gnn_g  = (const float*)d_in[8];
    const float* gnn_b  = (const float*)d_in[9];
    const float* bno_g  = (const float*)d_in[10];
    const float* bno_b  = (const float*)d_in[11];
    const float* W1     = (const float*)d_in[12];
    // d_in[13] = b1 : cancels
    const float* bn1_g  = (const float*)d_in[14];
    const float* bn1_b  = (const float*)d_in[15];
    const float* W2     = (const float*)d_in[16];
    // d_in[17] = b2 : cancels
    const float* bn2_g  = (const float*)d_in[18];
    const float* bn2_b  = (const float*)d_in[19];
    const float* W3     = (const float*)d_in[20];
    const float* b3     = (const float*)d_in[21];
    float* out = (float*)d_out;

    const int ATTN_SMEM = ATTN3_FLOATS * 4;   // 107,008 B -> 2 CTAs/SM
    cudaFuncSetAttribute(k_attn3, cudaFuncAttributeMaxDynamicSharedMemorySize,
                         ATTN_SMEM);

    k_graminit<<<dim3(16, 8), 256>>>(emb, lin_W, W1, W2, aem_i, aem_j);
    k_sel<<<128, 128>>>();
    k_gemm<0><<<dim3(M_ / 128, 1), 256>>>(data, att_i, att_j);
    k_attn3<<<dim3(4, B_), 512, ATTN_SMEM>>>();   // <- profiled slot
    k_h<<<M_ / 32, 256>>>(emb, gnn_g, gnn_b);
    k_gemm<1><<<dim3(M_ / 128, 2), 256>>>(nullptr, bno_g, bno_b);
    k_gemm<2><<<dim3(M_ / 128, 2), 256>>>(nullptr, bn1_g, bn1_b);
    k_out<<<M_ / 8, 256>>>(W3, b3, bn2_g, bn2_b, out);
}

// round 15
// speedup vs baseline: 1.0356x; 1.0356x over previous
#include <cuda_runtime.h>
#include <cuda_bf16.h>
#include <math.h>
#include <stdint.h>

#define B_ 64
#define N_ 512
#define D_ 128
#define K_ 32
#define M_ (B_ * N_)
#define EPS_ 1e-5f

typedef unsigned long long ull;
typedef unsigned short ushort_t;

// ---------------- device scratch ----------------
__device__ float g_xlin[M_ * D_];
__device__ float g_si[M_];
__device__ float g_sj[M_];
__device__ float g_ei[N_];
__device__ float g_ej[N_];
__device__ float g_cos[N_ * N_];
__device__ int   g_topk[N_ * K_];
__device__ float g_agg[M_ * D_];
__device__ float g_h[M_ * D_];
__device__ float g_o1[M_ * 256];
__device__ float g_o2[M_ * 256];
// W images: [n][k] row-major bf16, hi/lo split
__device__ __nv_bfloat16 g_Wh0[128 * 128], g_Wl0[128 * 128];
__device__ __nv_bfloat16 g_Wh1[256 * 128], g_Wl1[256 * 128];
__device__ __nv_bfloat16 g_Wh2[256 * 256], g_Wl2[256 * 256];
// stats: [0]=agg sum(128) [128]=agg sq [256]=h sum [384]=h sq
//        [512]=o1 sum(256) [768]=o1 sq [1024]=o2 sum [1280]=o2 sq
__device__ float g_red[1536];

// ---------------- helpers ----------------
__device__ __forceinline__ uint32_t smem_to_u32(const void* p) {
    uint32_t a;
    asm("{ .reg .u64 t; cvta.to.shared.u64 t, %1; cvt.u32.u64 %0, t; }"
        : "=r"(a) : "l"(p));
    return a;
}
__device__ __forceinline__ ushort_t bf_hi(float f, ushort_t& lo) {
    __nv_bfloat16 h = __float2bfloat16(f);
    float r = f - __bfloat162float(h);
    lo = __bfloat16_as_ushort(__float2bfloat16(r));
    return __bfloat16_as_ushort(h);
}
__device__ __forceinline__ ull pack4(ushort_t a, ushort_t b, ushort_t c, ushort_t d) {
    return (ull)a | ((ull)b << 16) | ((ull)c << 32) | ((ull)d << 48);
}
#define LDSM_X4(r0, r1, r2, r3, addr) \
    asm volatile("ldmatrix.sync.aligned.m8n8.x4.shared.b16 {%0,%1,%2,%3}, [%4];" \
                 : "=r"(r0), "=r"(r1), "=r"(r2), "=r"(r3) : "r"(addr))
#define MMA(dd, aa, b0v, b1v) \
    asm volatile("mma.sync.aligned.m16n8k16.row.col.f32.bf16.bf16.f32 " \
                 "{%0,%1,%2,%3}, {%4,%5,%6,%7}, {%8,%9}, {%0,%1,%2,%3};" \
                 : "+f"((dd)[0]), "+f"((dd)[1]), "+f"((dd)[2]), "+f"((dd)[3]) \
                 : "r"((aa)[0]), "r"((aa)[1]), "r"((aa)[2]), "r"((aa)[3]), \
                   "r"(b0v), "r"(b1v))

// ---------------- gram + init fused -----------------------------------------
__global__ __launch_bounds__(256) void k_graminit(const float* __restrict__ emb,
                                                  const float* __restrict__ linW,
                                                  const float* __restrict__ W1,
                                                  const float* __restrict__ W2,
                                                  const float* __restrict__ aei,
                                                  const float* __restrict__ aej) {
    __shared__ float Ash[128][32];
    __shared__ float Bsh[128][64];
    __shared__ float inviS[32], invjS[64];
    int t = threadIdx.x;
    int bx = blockIdx.x, by = blockIdx.y;
    int bid = by * 16 + bx;
    int gid = bid * 256 + t;

    if (gid < 1536) g_red[gid] = 0.0f;
    for (int id = gid; id < 114688; id += 32768) {
        if (id < 16384) {
            int k = id >> 7, n = id & 127;
            ushort_t lo; ushort_t hi = bf_hi(linW[k * 128 + n], lo);
            g_Wh0[n * 128 + k] = __ushort_as_bfloat16(hi);
            g_Wl0[n * 128 + k] = __ushort_as_bfloat16(lo);
        } else if (id < 49152) {
            int e = id - 16384;
            int k = e >> 8, n = e & 255;
            ushort_t lo; ushort_t hi = bf_hi(W1[k * 256 + n], lo);
            g_Wh1[n * 128 + k] = __ushort_as_bfloat16(hi);
            g_Wl1[n * 128 + k] = __ushort_as_bfloat16(lo);
        } else {
            int e = id - 49152;
            int k = e >> 8, n = e & 255;
            ushort_t lo; ushort_t hi = bf_hi(W2[k * 256 + n], lo);
            g_Wh2[n * 256 + k] = __ushort_as_bfloat16(hi);
            g_Wl2[n * 256 + k] = __ushort_as_bfloat16(lo);
        }
    }
    if (bid < 64) {
        int w = t >> 5, lane = t & 31;
        int n = bid * 8 + w;
        float4 v4 = *(const float4*)&emb[n * D_ + lane * 4];
        float4 ai4 = *(const float4*)&aei[lane * 4];
        float4 aj4 = *(const float4*)&aej[lane * 4];
        float pi = v4.x * ai4.x + v4.y * ai4.y + v4.z * ai4.z + v4.w * ai4.w;
        float pj = v4.x * aj4.x + v4.y * aj4.y + v4.z * aj4.z + v4.w * aj4.w;
        #pragma unroll
        for (int o = 16; o > 0; o >>= 1) {
            pi += __shfl_xor_sync(0xffffffffu, pi, o);
            pj += __shfl_xor_sync(0xffffffffu, pj, o);
        }
        if (lane == 0) { g_ei[n] = pi; g_ej[n] = pj; }
    }

    int i0 = bx * 32, j0 = by * 64;
    {
        int r = t & 31, kq0 = t >> 5;
        #pragma unroll
        for (int q = 0; q < 4; q++) {
            int kq = kq0 + q * 8;
            float4 a = *(const float4*)&emb[(i0 + r) * 128 + kq * 4];
            Ash[kq * 4 + 0][r] = a.x; Ash[kq * 4 + 1][r] = a.y;
            Ash[kq * 4 + 2][r] = a.z; Ash[kq * 4 + 3][r] = a.w;
        }
    }
    {
        int r = t & 63, kq0 = t >> 6;
        #pragma unroll
        for (int q = 0; q < 8; q++) {
            int kq = kq0 + q * 4;
            float4 b = *(const float4*)&emb[(j0 + r) * 128 + kq * 4];
            Bsh[kq * 4 + 0][r] = b.x; Bsh[kq * 4 + 1][r] = b.y;
            Bsh[kq * 4 + 2][r] = b.z; Bsh[kq * 4 + 3][r] = b.w;
        }
    }
    __syncthreads();
    if (t < 32) {
        float s = 0.0f;
        #pragma unroll 8
        for (int k = 0; k < 128; k++) { float v = Ash[k][t]; s += v * v; }
        inviS[t] = 1.0f / sqrtf(s);
    } else if (t < 96) {
        int r = t - 32;
        float s = 0.0f;
        #pragma unroll 8
        for (int k = 0; k < 128; k++) { float v = Bsh[k][r]; s += v * v; }
        invjS[r] = 1.0f / sqrtf(s);
    }
    __syncthreads();
    int tr = t >> 4, tc = t & 15;
    float acc[2][4] = {};
    #pragma unroll 4
    for (int k = 0; k < 128; k++) {
        float2 av = *(float2*)&Ash[k][tr * 2];
        float4 bv = *(float4*)&Bsh[k][tc * 4];
        acc[0][0] += av.x * bv.x; acc[0][1] += av.x * bv.y;
        acc[0][2] += av.x * bv.z; acc[0][3] += av.x * bv.w;
        acc[1][0] += av.y * bv.x; acc[1][1] += av.y * bv.y;
        acc[1][2] += av.y * bv.z; acc[1][3] += av.y * bv.w;
    }
    float invi[2], invj[4];
    #pragma unroll
    for (int q = 0; q < 2; q++) invi[q] = inviS[tr * 2 + q];
    #pragma unroll
    for (int q = 0; q < 4; q++) invj[q] = invjS[tc * 4 + q];
    #pragma unroll
    for (int rr = 0; rr < 2; rr++) {
        float s = invi[rr];
        *(float4*)&g_cos[(i0 + tr * 2 + rr) * N_ + j0 + tc * 4] =
            make_float4(acc[rr][0] * s * invj[0], acc[rr][1] * s * invj[1],
                        acc[rr][2] * s * invj[2], acc[rr][3] * s * invj[3]);
    }
}

// ---------------- topk selection: one warp per row ----------------
__global__ __launch_bounds__(256) void k_sel() {
    __shared__ float sv[8][512];
    int t = threadIdx.x, w = t >> 5, lane = t & 31;
    int i = blockIdx.x * 8 + w;
    float* v = sv[w];
    #pragma unroll
    for (int q = 0; q < 16; q++)
        v[q * 32 + lane] = g_cos[i * N_ + q * 32 + lane];
    float lv = v[lane]; int li = 0;
    #pragma unroll
    for (int q = 1; q < 16; q++) {
        float x = v[q * 32 + lane];
        if (x > lv) { lv = x; li = q; }
    }
    for (int k = 0; k < K_; k++) {
        float bv = lv;
        int bj = li * 32 + lane;
        #pragma unroll
        for (int o = 16; o > 0; o >>= 1) {
            float ov = __shfl_xor_sync(0xffffffffu, bv, o);
            int oj = __shfl_xor_sync(0xffffffffu, bj, o);
            if (ov > bv || (ov == bv && oj < bj)) { bv = ov; bj = oj; }
        }
        if (lane == 0) g_topk[i * K_ + k] = bj;
        if ((bj & 31) == lane) {
            v[bj] = -2.0f;
            lv = v[lane]; li = 0;
            #pragma unroll
            for (int q = 1; q < 16; q++) {
                float x = v[q * 32 + lane];
                if (x > lv) { lv = x; li = q; }
            }
        }
        __syncwarp();
    }
}

// ---------------- unified HMMA GEMM (3-term bf16 split, R10 config) ---------
template <int PASS>
__global__ __launch_bounds__(256) void k_gemm(const float* __restrict__ Xext,
                                              const float* __restrict__ gin,
                                              const float* __restrict__ bin) {
    constexpr int KD   = (PASS == 2) ? 256 : 128;
    constexpr int OSTR = (PASS == 0) ? 128 : 256;
    constexpr int SIN  = (PASS == 1) ? 256 : 512;
    constexpr int SOUT = (PASS == 1) ? 512 : 1024;

    __shared__ __align__(16) __nv_bfloat16 Xh[128 * 40];
    __shared__ __align__(16) __nv_bfloat16 Xl[128 * 40];
    __shared__ __align__(16) __nv_bfloat16 Wh[128 * 40];
    __shared__ __align__(16) __nv_bfloat16 Wl[128 * 40];
    __shared__ float nsc[256], nsh[256];
    __shared__ float sbS[4][128], sbQ[4][128];

    const float* __restrict__ Xg =
        (PASS == 0) ? Xext : ((PASS == 1) ? g_h : g_o1);
    float* __restrict__ outg =
        (PASS == 0) ? g_xlin : ((PASS == 1) ? g_o1 : g_o2);
    const __nv_bfloat16* Wgh = (PASS == 0) ? g_Wh0 : ((PASS == 1) ? g_Wh1 : g_Wh2);
    const __nv_bfloat16* Wgl = (PASS == 0) ? g_Wl0 : ((PASS == 1) ? g_Wl1 : g_Wl2);

    int t = threadIdx.x, l = t & 31, w = t >> 5;
    int wr = w >> 1, wc = w & 1;
    int row0 = blockIdx.x * 128;
    int nb = blockIdx.y;
    const __nv_bfloat16* WghB = Wgh + nb * 128 * KD;
    const __nv_bfloat16* WglB = Wgl + nb * 128 * KD;

    if (PASS != 0) {
        const float invM = 1.0f / (float)M_;
        if (t < KD) {
            float mean = g_red[SIN + t] * invM;
            float var  = g_red[SIN + KD + t] * invM - mean * mean;
            float s = rsqrtf(var + EPS_) * gin[t];
            nsc[t] = s; nsh[t] = bin[t] - mean * s;
        }
        __syncthreads();
    } else {
        if (t < 128) { nsc[t] = gin[t]; nsh[t] = bin[t]; }  // att_i, att_j
        __syncthreads();
    }

    float d[2][8][4] = {};
    uint32_t xh_b = smem_to_u32(Xh), xl_b = smem_to_u32(Xl);
    uint32_t wh_b = smem_to_u32(Wh), wl_b = smem_to_u32(Wl);

    for (int kb = 0; kb < KD; kb += 32) {
        #pragma unroll
        for (int v = t; v < 1024; v += 256) {
            int r = v >> 3, k4 = (v & 7) * 4;
            float4 x4 = *(const float4*)&Xg[(row0 + r) * KD + kb + k4];
            float f0, f1, f2, f3;
            if (PASS == 0) {
                f0 = x4.x; f1 = x4.y; f2 = x4.z; f3 = x4.w;
            } else {
                int fc = kb + k4;
                f0 = fmaxf(x4.x * nsc[fc + 0] + nsh[fc + 0], 0.0f);
                f1 = fmaxf(x4.y * nsc[fc + 1] + nsh[fc + 1], 0.0f);
                f2 = fmaxf(x4.z * nsc[fc + 2] + nsh[fc + 2], 0.0f);
                f3 = fmaxf(x4.w * nsc[fc + 3] + nsh[fc + 3], 0.0f);
            }
            ushort_t l0, l1, l2, l3;
            ushort_t h0 = bf_hi(f0, l0), h1 = bf_hi(f1, l1);
            ushort_t h2 = bf_hi(f2, l2), h3 = bf_hi(f3, l3);
            *(ull*)(&Xh[r * 40 + k4]) = pack4(h0, h1, h2, h3);
            *(ull*)(&Xl[r * 40 + k4]) = pack4(l0, l1, l2, l3);
        }
        #pragma unroll
        for (int v = t; v < 512; v += 256) {
            int n = v >> 2, k8 = (v & 3) * 8;
            *(float4*)&Wh[n * 40 + k8] = *(const float4*)&WghB[n * KD + kb + k8];
            *(float4*)&Wl[n * 40 + k8] = *(const float4*)&WglB[n * KD + kb + k8];
        }
        __syncthreads();
        #pragma unroll
        for (int ks = 0; ks < 32; ks += 16) {
            uint32_t ah[2][4], al[2][4];
            uint32_t arow = (uint32_t)(l & 15);
            uint32_t akoff = (uint32_t)((l >> 4) << 3);
            #pragma unroll
            for (int mt = 0; mt < 2; mt++) {
                uint32_t off = ((wr * 32 + mt * 16 + arow) * 40 + ks + akoff) * 2;
                LDSM_X4(ah[mt][0], ah[mt][1], ah[mt][2], ah[mt][3], xh_b + off);
                LDSM_X4(al[mt][0], al[mt][1], al[mt][2], al[mt][3], xl_b + off);
            }
            uint32_t brow = (uint32_t)(((l >> 4) << 3) + (l & 7));
            uint32_t bkoff = (uint32_t)(((l >> 3) & 1) << 3);
            #pragma unroll
            for (int g = 0; g < 4; g++) {
                uint32_t off = ((wc * 64 + g * 16 + brow) * 40 + ks + bkoff) * 2;
                uint32_t bh[4], bl[4];
                LDSM_X4(bh[0], bh[1], bh[2], bh[3], wh_b + off);
                LDSM_X4(bl[0], bl[1], bl[2], bl[3], wl_b + off);
                MMA(d[0][2 * g],     ah[0], bh[0], bh[1]);
                MMA(d[0][2 * g + 1], ah[0], bh[2], bh[3]);
                MMA(d[1][2 * g],     ah[1], bh[0], bh[1]);
                MMA(d[1][2 * g + 1], ah[1], bh[2], bh[3]);
                MMA(d[0][2 * g],     ah[0], bl[0], bl[1]);
                MMA(d[0][2 * g + 1], ah[0], bl[2], bl[3]);
                MMA(d[1][2 * g],     ah[1], bl[0], bl[1]);
                MMA(d[1][2 * g + 1], ah[1], bl[2], bl[3]);
                MMA(d[0][2 * g],     al[0], bh[0], bh[1]);
                MMA(d[0][2 * g + 1], al[0], bh[2], bh[3]);
                MMA(d[1][2 * g],     al[1], bh[0], bh[1]);
                MMA(d[1][2 * g + 1], al[1], bh[2], bh[3]);
            }
        }
        __syncthreads();
    }

    int rbase = row0 + wr * 32 + (l >> 2);
    int cbase = nb * 128 + wc * 64 + (l & 3) * 2;
    #pragma unroll
    for (int mt = 0; mt < 2; mt++) {
        #pragma unroll
        for (int nt = 0; nt < 8; nt++) {
            int col = cbase + nt * 8;
            *(float2*)&outg[(rbase + mt * 16) * OSTR + col] =
                make_float2(d[mt][nt][0], d[mt][nt][1]);
            *(float2*)&outg[(rbase + mt * 16 + 8) * OSTR + col] =
                make_float2(d[mt][nt][2], d[mt][nt][3]);
        }
    }
    if (PASS != 0) {
        #pragma unroll
        for (int nt = 0; nt < 8; nt++) {
            float c0 = d[0][nt][0] + d[0][nt][2] + d[1][nt][0] + d[1][nt][2];
            float c1 = d[0][nt][1] + d[0][nt][3] + d[1][nt][1] + d[1][nt][3];
            float q0 = d[0][nt][0] * d[0][nt][0] + d[0][nt][2] * d[0][nt][2] +
                       d[1][nt][0] * d[1][nt][0] + d[1][nt][2] * d[1][nt][2];
            float q1 = d[0][nt][1] * d[0][nt][1] + d[0][nt][3] * d[0][nt][3] +
                       d[1][nt][1] * d[1][nt][1] + d[1][nt][3] * d[1][nt][3];
            #pragma unroll
            for (int o = 4; o <= 16; o <<= 1) {
                c0 += __shfl_xor_sync(0xffffffffu, c0, o);
                c1 += __shfl_xor_sync(0xffffffffu, c1, o);
                q0 += __shfl_xor_sync(0xffffffffu, q0, o);
                q1 += __shfl_xor_sync(0xffffffffu, q1, o);
            }
            if (l < 4) {
                sbS[wr][wc * 64 + nt * 8 + l * 2]     = c0;
                sbS[wr][wc * 64 + nt * 8 + l * 2 + 1] = c1;
                sbQ[wr][wc * 64 + nt * 8 + l * 2]     = q0;
                sbQ[wr][wc * 64 + nt * 8 + l * 2 + 1] = q1;
            }
        }
        __syncthreads();
        if (t < 128) {
            float S = sbS[0][t] + sbS[1][t] + sbS[2][t] + sbS[3][t];
            float Q = sbQ[0][t] + sbQ[1][t] + sbQ[2][t] + sbQ[3][t];
            atomicAdd(&g_red[SOUT + nb * 128 + t], S);
            atomicAdd(&g_red[SOUT + 256 + nb * 128 + t], Q);
        }
    } else {
        #pragma unroll
        for (int mt = 0; mt < 2; mt++) {
            float p0 = 0, p1 = 0, pj0 = 0, pj1 = 0;
            #pragma unroll
            for (int nt = 0; nt < 8; nt++) {
                int c = wc * 64 + (l & 3) * 2 + nt * 8;
                p0  += d[mt][nt][0] * nsc[c] + d[mt][nt][1] * nsc[c + 1];
                p1  += d[mt][nt][2] * nsc[c] + d[mt][nt][3] * nsc[c + 1];
                pj0 += d[mt][nt][0] * nsh[c] + d[mt][nt][1] * nsh[c + 1];
                pj1 += d[mt][nt][2] * nsh[c] + d[mt][nt][3] * nsh[c + 1];
            }
            #pragma unroll
            for (int o = 1; o <= 2; o <<= 1) {
                p0  += __shfl_xor_sync(0xffffffffu, p0, o);
                p1  += __shfl_xor_sync(0xffffffffu, p1, o);
                pj0 += __shfl_xor_sync(0xffffffffu, pj0, o);
                pj1 += __shfl_xor_sync(0xffffffffu, pj1, o);
            }
            if ((l & 3) == 0) {
                int rl = wr * 32 + mt * 16 + (l >> 2);
                sbS[wc * 2][rl]     = p0;
                sbS[wc * 2][rl + 8] = p1;
                sbQ[wc * 2][rl]     = pj0;
                sbQ[wc * 2][rl + 8] = pj1;
            }
        }
        __syncthreads();
        if (t < 128) {
            int row = row0 + t;
            int n = row & (N_ - 1);
            g_si[row] = sbS[0][t] + sbS[2][t] + g_ei[n];
            g_sj[row] = sbQ[0][t] + sbQ[2][t] + g_ej[n];
        }
    }
}

// ---------------- attention v3 (R13) + list-entry prefetch ------------------
// grid (4, B_), 512 threads. smem layout (floats):
// [0,16384)        xwin: 128 rows x 128 cols fp32 (64KB), current window
// [16384,25088)    list: float2[128 nodes][34] (alpha, byte-offset)
// [25088,25728)    cb:   int[128][5] window segment boundaries
#define ATTN3_FLOATS (16384 + 8704 + 640)
__global__ __launch_bounds__(512, 2) void k_attn3() {
    extern __shared__ float dsm[];
    float*  xwin = dsm;
    float2* list = (float2*)(dsm + 16384);
    int*    cb   = (int*)(dsm + 16384 + 8704);

    int t = threadIdx.x, lane = t & 31, w = t >> 5;  // 16 warps
    int b = blockIdx.y, i0 = blockIdx.x * 128;

    // ---- build per-node compacted edge lists, partitioned by 128-row window
    #pragma unroll
    for (int q = 0; q < 8; q++) {
        int mi = w * 8 + q;
        int i = i0 + mi;
        int m = b * N_ + i;
        int src = g_topk[i * K_ + lane];
        float sim = g_si[m];
        float v = sim + g_sj[b * N_ + src];
        float lg = v > 0.0f ? v : 0.2f * v;
        bool valid = (src != i);
        if (!valid) lg = -1e30f;
        float vs = sim + g_sj[m];
        float lgs = vs > 0.0f ? vs : 0.2f * vs;   // explicit self loop
        float mx = lg;
        #pragma unroll
        for (int o = 16; o > 0; o >>= 1)
            mx = fmaxf(mx, __shfl_xor_sync(0xffffffffu, mx, o));
        mx = fmaxf(mx, lgs);
        float e = valid ? expf(lg - mx) : 0.0f;
        float es = expf(lgs - mx);
        float den = e;
        #pragma unroll
        for (int o = 16; o > 0; o >>= 1)
            den += __shfl_xor_sync(0xffffffffu, den, o);
        den += es;
        float alpha = e / den;
        float aself = es / den;
        int win = src >> 7;
        int selfwin = i >> 7;
        unsigned lt = (1u << lane) - 1u;
        int base = 0;
        #pragma unroll
        for (int wn = 0; wn < 4; wn++) {
            unsigned mk = __ballot_sync(0xffffffffu, valid && win == wn);
            if (lane == 0) cb[mi * 5 + wn] = base;
            if (valid && win == wn) {
                int pos = base + __popc(mk & lt);
                list[mi * 34 + pos] =
                    make_float2(alpha, __uint_as_float((uint32_t)((src & 127) * 512)));
            }
            if (lane == 0 && selfwin == wn) {
                int pos = base + __popc(mk);
                list[mi * 34 + pos] =
                    make_float2(aself, __uint_as_float((uint32_t)((i & 127) * 512)));
            }
            base += __popc(mk) + (selfwin == wn ? 1 : 0);
        }
        if (lane == 0) cb[mi * 5 + 4] = base;
    }

    uint32_t xwin_b = smem_to_u32(xwin);
    float acc[8][4] = {};
    for (int win = 0; win < 4; win++) {
        __syncthreads();
        const float4* srcp = (const float4*)&g_xlin[(b * N_ + win * 128) * D_];
        #pragma unroll
        for (int v = t; v < 4096; v += 512)
            ((float4*)xwin)[v] = srcp[v];
        __syncthreads();
        uint32_t loff = (uint32_t)(lane * 16);
        #pragma unroll
        for (int q = 0; q < 8; q++) {
            int mi = w * 8 + q;
            int s = cb[mi * 5 + win], e = cb[mi * 5 + win + 1];
            const float2* lp = &list[mi * 34];
            // prefetch: next list entry load overlaps current row load.
            // lp[p+1] for p+1 <= 33 is always within the 34-slot array;
            // the value read past the segment end is discarded.
            float2 cv = lp[s];
            for (int p = s; p < e; p++) {
                float2 nv = lp[p + 1];
                uint32_t off = __float_as_uint(cv.y);
                float a = cv.x;
                float4 xv;
                asm volatile("ld.shared.v4.f32 {%0,%1,%2,%3}, [%4];"
                             : "=f"(xv.x), "=f"(xv.y), "=f"(xv.z), "=f"(xv.w)
                             : "r"(xwin_b + off + loff));
                acc[q][0] += a * xv.x; acc[q][1] += a * xv.y;
                acc[q][2] += a * xv.z; acc[q][3] += a * xv.w;
                cv = nv;
            }
        }
    }
    __syncthreads();
    // ---- write agg + fused stats (reuse xwin region) ----
    float s[4] = {}, qd[4] = {};
    #pragma unroll
    for (int q = 0; q < 8; q++) {
        int m = b * N_ + i0 + w * 8 + q;
        *(float4*)&g_agg[m * D_ + lane * 4] =
            make_float4(acc[q][0], acc[q][1], acc[q][2], acc[q][3]);
        #pragma unroll
        for (int c = 0; c < 4; c++) { s[c] += acc[q][c]; qd[c] += acc[q][c] * acc[q][c]; }
    }
    float* sS = dsm;
    float* sQ = dsm + 2048;
    #pragma unroll
    for (int c = 0; c < 4; c++) {
        sS[w * 128 + lane * 4 + c] = s[c];
        sQ[w * 128 + lane * 4 + c] = qd[c];
    }
    __syncthreads();
    if (t < 128) {
        float S = 0, Q = 0;
        #pragma unroll
        for (int g = 0; g < 16; g++) { S += sS[g * 128 + t]; Q += sQ[g * 128 + t]; }
        atomicAdd(&g_red[t], S);
        atomicAdd(&g_red[128 + t], Q);
    }
}

// ---------------- gcn = relu(bn(agg)); h = gcn*emb + h stats ----------------
__global__ __launch_bounds__(256) void k_h(const float* __restrict__ emb,
                                           const float* __restrict__ g0,
                                           const float* __restrict__ b0) {
    __shared__ float sS[8][128], sQ[8][128];
    int t = threadIdx.x, w = t >> 5, lane = t & 31;
    int r0 = blockIdx.x * 64 + w * 8;
    const float invM = 1.0f / (float)M_;
    int d4 = lane * 4;
    float4 sm = *(float4*)&g_red[d4];
    float4 sq = *(float4*)&g_red[D_ + d4];
    float4 gg = *(const float4*)&g0[d4];
    float4 bb = *(const float4*)&b0[d4];
    float mean0 = sm.x * invM, mean1 = sm.y * invM, mean2 = sm.z * invM, mean3 = sm.w * invM;
    float sc0 = rsqrtf(sq.x * invM - mean0 * mean0 + EPS_) * gg.x;
    float sc1 = rsqrtf(sq.y * invM - mean1 * mean1 + EPS_) * gg.y;
    float sc2 = rsqrtf(sq.z * invM - mean2 * mean2 + EPS_) * gg.z;
    float sc3 = rsqrtf(sq.w * invM - mean3 * mean3 + EPS_) * gg.w;
    float sh0 = bb.x - mean0 * sc0, sh1 = bb.y - mean1 * sc1;
    float sh2 = bb.z - mean2 * sc2, sh3 = bb.w - mean3 * sc3;
    float S[4] = {}, Q[4] = {};
    #pragma unroll
    for (int r = 0; r < 8; r++) {
        int row = r0 + r;
        float4 a = *(float4*)&g_agg[row * D_ + d4];
        float4 e = *(const float4*)&emb[(row & (N_ - 1)) * D_ + d4];
        float h0 = fmaxf(a.x * sc0 + sh0, 0.0f) * e.x;
        float h1 = fmaxf(a.y * sc1 + sh1, 0.0f) * e.y;
        float h2 = fmaxf(a.z * sc2 + sh2, 0.0f) * e.z;
        float h3 = fmaxf(a.w * sc3 + sh3, 0.0f) * e.w;
        *(float4*)&g_h[row * D_ + d4] = make_float4(h0, h1, h2, h3);
        S[0] += h0; S[1] += h1; S[2] += h2; S[3] += h3;
        Q[0] += h0 * h0; Q[1] += h1 * h1; Q[2] += h2 * h2; Q[3] += h3 * h3;
    }
    #pragma unroll
    for (int c = 0; c < 4; c++) { sS[w][d4 + c] = S[c]; sQ[w][d4 + c] = Q[c]; }
    __syncthreads();
    if (t < 128) {
        float Ss = 0, Qs = 0;
        #pragma unroll
        for (int g = 0; g < 8; g++) { Ss += sS[g][t]; Qs += sQ[g][t]; }
        atomicAdd(&g_red[256 + t], Ss);
        atomicAdd(&g_red[384 + t], Qs);
    }
}

// ---------------- final: out = relu(bn(o2)) @ W3 + b3 ----------------
__global__ __launch_bounds__(256) void k_out(const float* __restrict__ W3,
                                             const float* __restrict__ b3,
                                             const float* __restrict__ g2,
                                             const float* __restrict__ b2v,
                                             float* __restrict__ out) {
    __shared__ float nsc[256], nsh[256], w[256];
    int t = threadIdx.x;
    const float invM = 1.0f / (float)M_;
    {
        float mean = g_red[1024 + t] * invM;
        float var  = g_red[1280 + t] * invM - mean * mean;
        float s = rsqrtf(var + EPS_) * g2[t];
        nsc[t] = s; nsh[t] = b2v[t] - mean * s; w[t] = W3[t];
    }
    __syncthreads();
    int warp = t >> 5, lane = t & 31;
    int m = blockIdx.x * 8 + warp;
    float acc = 0.0f;
    #pragma unroll
    for (int f = lane; f < 256; f += 32) {
        float v = g_o2[m * 256 + f];
        acc += fmaxf(v * nsc[f] + nsh[f], 0.0f) * w[f];
    }
    for (int o = 16; o > 0; o >>= 1)
        acc += __shfl_xor_sync(0xffffffffu, acc, o);
    if (lane == 0) out[m] = acc + b3[0];
}

// ---------------- launch ----------------
extern "C" void kernel_launch(void* const* d_in, const int* in_sizes, int n_in,
                              void* d_out, int out_size) {
    const float* data   = (const float*)d_in[0];
    const float* emb    = (const float*)d_in[1];
    const float* lin_W  = (const float*)d_in[2];
    const float* att_i  = (const float*)d_in[3];
    const float* att_j  = (const float*)d_in[4];
    const float* aem_i  = (const float*)d_in[5];
    const float* aem_j  = (const float*)d_in[6];
    // d_in[7] = gnn_bias : cancels exactly under BN
    const float* gnn_g  = (const float*)d_in[8];
    const float* gnn_b  = (const float*)d_in[9];
    const float* bno_g  = (const float*)d_in[10];
    const float* bno_b  = (const float*)d_in[11];
    const float* W1     = (const float*)d_in[12];
    // d_in[13] = b1 : cancels
    const float* bn1_g  = (const float*)d_in[14];
    const float* bn1_b  = (const float*)d_in[15];
    const float* W2     = (const float*)d_in[16];
    // d_in[17] = b2 : cancels
    const float* bn2_g  = (const float*)d_in[18];
    const float* bn2_b  = (const float*)d_in[19];
    const float* W3     = (const float*)d_in[20];
    const float* b3     = (const float*)d_in[21];
    float* out = (float*)d_out;

    const int ATTN_SMEM = ATTN3_FLOATS * 4;   // 102,912 B -> 2 CTAs/SM
    cudaFuncSetAttribute(k_attn3, cudaFuncAttributeMaxDynamicSharedMemorySize,
                         ATTN_SMEM);

    k_graminit<<<dim3(16, 8), 256>>>(emb, lin_W, W1, W2, aem_i, aem_j);
    k_sel<<<64, 256>>>();
    k_gemm<0><<<dim3(M_ / 128, 1), 256>>>(data, att_i, att_j);
    k_attn3<<<dim3(4, B_), 512, ATTN_SMEM>>>();   // <- profiled slot
    k_h<<<M_ / 64, 256>>>(emb, gnn_g, gnn_b);
    k_gemm<1><<<dim3(M_ / 128, 2), 256>>>(nullptr, bno_g, bno_b);
    k_gemm<2><<<dim3(M_ / 128, 2), 256>>>(nullptr, bn1_g, bn1_b);
    k_out<<<M_ / 8, 256>>>(W3, b3, bn2_g, bn2_b, out);
}